// round 15
// baseline (speedup 1.0000x reference)
#include <cuda_runtime.h>
#include <cuda_fp16.h>
#include <math.h>
#include <stdint.h>

#define B 4096
#define D 128
#define NT 32              // 4096 / 128 tiles per dimension
#define NTILES_T 528       // NT*(NT+1)/2 upper-triangle tiles
#define NBLK 296           // 148 SMs x 2 CTAs: all co-resident (wave 1)
#define NCLS 64
#define PB 1024
#define PAIR_CAP (1 << 20)
#define CEXP 16.0f         // accumulate exp(CEXP - dist); fixup in loss phase

// ---- scratch (device globals; no allocation allowed) ----
__device__ float    g_rowneg[B];
__device__ float    g_mag[B];
__device__ int      g_t32[B];
__device__ int      g_npairs;
__device__ unsigned g_done;
__device__ unsigned g_done2;
__device__ float    g_pair_d[PAIR_CAP];
__device__ unsigned g_pair_ij[PAIR_CAP];
__device__ double   g_loss;
__device__ __align__(256) __half g_h16[(size_t)B * D];

static __device__ __forceinline__ uint32_t smem_u32(const void* p) {
    uint32_t a;
    asm("{ .reg .u64 t; cvta.to.shared.u64 t, %1; cvt.u32.u64 %0, t; }"
        : "=r"(a) : "l"(p));
    return a;
}

// ---- smem: full-K tiles A,B 128 x 128 fp16, row stride 272 B ----
#define LDT 272
#define TILE_B 34816       // 128 * 272
#define OFF_A    0
#define OFF_B    34816
#define OFF_MAGI 69632
#define OFF_MAGJ 70144
#define OFF_TI   70656
#define OFF_TJ   71168
#define OFF_RBUF 71680
#define OFF_CBUF 72192
#define OFF_PSD  72704
#define OFF_PSIJ 76800
#define OFF_PSN  80896
#define OFF_PSBASE 80900
#define SMEM_TOTAL 80960

#define LDSM4(r0, r1, r2, r3, a)                                         \
    asm volatile("ldmatrix.sync.aligned.m8n8.x4.shared.b16 "             \
                 "{%0,%1,%2,%3}, [%4];"                                  \
                 : "=r"(r0), "=r"(r1), "=r"(r2), "=r"(r3) : "r"(a))

#define MMA_F16(c, a0, a1, a2, a3, b0, b1)                               \
    asm volatile("mma.sync.aligned.m16n8k16.row.col.f32.f16.f16.f32 "    \
                 "{%0,%1,%2,%3}, {%4,%5,%6,%7}, {%8,%9}, {%0,%1,%2,%3};" \
                 : "+f"((c)[0]), "+f"((c)[1]), "+f"((c)[2]), "+f"((c)[3])\
                 : "r"(a0), "r"(a1), "r"(a2), "r"(a3), "r"(b0), "r"(b1))

#define CP_ASYNC16(s, g)                                                 \
    asm volatile("cp.async.cg.shared.global [%0], [%1], 16;"             \
                 :: "r"(s), "l"(g))
#define CP_COMMIT() asm volatile("cp.async.commit_group;" ::: "memory")
#define CP_WAIT0()  asm volatile("cp.async.wait_group 0;" ::: "memory")

static __device__ __forceinline__ uint32_t pack_h2(float lo, float hi) {
    uint32_t r;
    asm("cvt.rn.f16x2.f32 %0, %1, %2;" : "=r"(r) : "f"(hi), "f"(lo));
    return r;
}
static __device__ __forceinline__ float sqrt_approx(float x) {
    float r;
    asm("sqrt.approx.f32 %0, %1;" : "=f"(r) : "f"(x));
    return r;
}
static __device__ __forceinline__ uint32_t hadd2_u(uint32_t a, uint32_t b) {
    uint32_t r;
    asm("add.rn.f16x2 %0, %1, %2;" : "=r"(r) : "r"(a), "r"(b));
    return r;
}

// ---------------------------------------------------------------------------
// K1: fused prep — fp16 copy, exact fp32 magnitudes, labels, zero scalars
// ---------------------------------------------------------------------------
__global__ void __launch_bounds__(256) k_prep(const float* __restrict__ X,
                                              const int* __restrict__ T) {
    int warp = threadIdx.x >> 5, lane = threadIdx.x & 31;
    int row  = blockIdx.x * 8 + warp;
    const float4* xr = (const float4*)(X + (size_t)row * D);
    float4 v = xr[lane];
    uint2 hp = { pack_h2(v.x, v.y), pack_h2(v.z, v.w) };
    ((uint2*)(g_h16 + (size_t)row * D))[lane] = hp;
    float s = v.x * v.x + v.y * v.y + v.z * v.z + v.w * v.w;
    #pragma unroll
    for (int off = 16; off; off >>= 1) s += __shfl_xor_sync(0xffffffff, s, off);
    if (lane == 0) {
        g_mag[row]    = s;
        g_t32[row]    = T[row] & (NCLS - 1);
        g_rowneg[row] = 0.f;
    }
    if (blockIdx.x == 0 && threadIdx.x == 0) {
        g_loss = 0.0; g_npairs = 0; g_done = 0u; g_done2 = 0u;
    }
}

// decode triangular tile index -> (i0, j0)
static __device__ __forceinline__ void decode_tile(int t, int& i0, int& j0) {
    int bi = 0, rem = t;
    while (rem >= NT - bi) { rem -= NT - bi; bi++; }
    i0 = bi * 128;
    j0 = (bi + rem) * 128;
}

// issue the FULL K=128 tiles (A: rows i0.., B: rows j0..) via cp.async
static __device__ __forceinline__ void issue_full(uint32_t sb, int tid,
                                                  int i0, int j0) {
    #pragma unroll
    for (int it = 0; it < 16; it++) {
        int e    = it * 256 + tid;       // 0..4095 16B ops
        int tile = e >> 11;              // 0=A, 1=B
        int w    = e & 2047;
        int r    = w >> 4, kc = w & 15;
        int row0 = tile ? j0 : i0;
        CP_ASYNC16(sb + tile * TILE_B + r * LDT + kc * 16,
                   g_h16 + (size_t)(row0 + r) * D + kc * 8);
    }
    CP_COMMIT();
}

// ---------------------------------------------------------------------------
// K2: persistent fused kernel — Gram tiles + grid barrier + pair loss + out
// ---------------------------------------------------------------------------
__global__ void __launch_bounds__(256, 2) k_dist(float* __restrict__ out) {
    extern __shared__ char smem[];
    uint32_t sb = smem_u32(smem);
    int tid = threadIdx.x;
    int wid = tid >> 5, lane = tid & 31;
    int wm = wid & 1, wn = wid >> 1;      // 2 x 4 warp grid, 64x32 each

    float* magis = (float*)(smem + OFF_MAGI);
    float* magjs = (float*)(smem + OFF_MAGJ);
    int*   tis   = (int*)(smem + OFF_TI);
    int*   tjs   = (int*)(smem + OFF_TJ);
    float* rbuf  = (float*)(smem + OFF_RBUF);
    float* cbuf  = (float*)(smem + OFF_CBUF);
    float* psd = (float*)(smem + OFF_PSD);
    unsigned* psij = (unsigned*)(smem + OFF_PSIJ);
    int* psn = (int*)(smem + OFF_PSN);

    uint32_t aRowOff = ((lane & 7) + ((lane >> 3) & 1) * 8) * LDT + (lane >> 4) * 16;
    uint32_t bRowOff = ((lane & 7) + (lane >> 4) * 8) * LDT + ((lane >> 3) & 1) * 16;
    uint32_t aBase = sb + OFF_A + wm * 64 * LDT + aRowOff;
    uint32_t bBase = sb + OFF_B + wn * 32 * LDT + bRowOff;

    const __half2 kA = __floats2half2_rn(-1.44269504f, -1.44269504f);
    const __half2 kB = __floats2half2_rn(CEXP * 1.44269504f, CEXP * 1.44269504f);

    // prologue: issue first tile's loads
    {
        int i0p, j0p;
        decode_tile(blockIdx.x, i0p, j0p);
        issue_full(sb, tid, i0p, j0p);
    }

    for (int t = blockIdx.x; t < NTILES_T; t += NBLK) {
        int i0, j0;
        decode_tile(t, i0, j0);

        if (tid == 0) *psn = 0;
        if (tid < 128) {
            magis[tid] = g_mag[i0 + tid];
            magjs[tid] = g_mag[j0 + tid];
            tis[tid]   = g_t32[i0 + tid];
            tjs[tid]   = g_t32[j0 + tid];
            rbuf[tid] = 0.f; cbuf[tid] = 0.f;
        }

        float acc[4][4][4];
        #pragma unroll
        for (int mt = 0; mt < 4; mt++)
            #pragma unroll
            for (int nt = 0; nt < 4; nt++)
                #pragma unroll
                for (int q = 0; q < 4; q++) acc[mt][nt][q] = 0.f;

        CP_WAIT0();
        __syncthreads();

        #pragma unroll
        for (int ks = 0; ks < 8; ks++) {
            uint32_t ko = ks * 32;
            uint32_t bh[8];
            LDSM4(bh[0], bh[1], bh[2], bh[3], bBase + ko);
            LDSM4(bh[4], bh[5], bh[6], bh[7], bBase + 16 * LDT + ko);
            #pragma unroll
            for (int mt = 0; mt < 4; mt++) {
                uint32_t ah[4];
                LDSM4(ah[0], ah[1], ah[2], ah[3], aBase + mt * 16 * LDT + ko);
                #pragma unroll
                for (int nt = 0; nt < 4; nt++)
                    MMA_F16(acc[mt][nt], ah[0], ah[1], ah[2], ah[3],
                            bh[nt * 2], bh[nt * 2 + 1]);
            }
        }
        __syncthreads();                  // all LDSM reads complete

        // prefetch next tile behind the epilogue
        if (t + NBLK < NTILES_T) {
            int i0n, j0n;
            decode_tile(t + NBLK, i0n, j0n);
            issue_full(sb, tid, i0n, j0n);
        }

        // --- f16x2 register epilogue ---
        int qr = lane >> 2, qc2 = (lane & 3) * 2;

        float magi_r[8]; int ti_r[8];
        #pragma unroll
        for (int mt = 0; mt < 4; mt++)
            #pragma unroll
            for (int h = 0; h < 2; h++) {
                int rl = wm * 64 + mt * 16 + qr + h * 8;
                magi_r[mt * 2 + h] = magis[rl];
                ti_r[mt * 2 + h]   = tis[rl];
            }

        uint32_t row_h2[8] = {0,0,0,0,0,0,0,0};
        uint32_t col_h2[4] = {0,0,0,0};

        #pragma unroll
        for (int nt = 0; nt < 4; nt++) {
            int cl = wn * 32 + nt * 8 + qc2;
            float mj0 = magjs[cl], mj1 = magjs[cl + 1];
            int   tj0 = tjs[cl],   tj1 = tjs[cl + 1];
            #pragma unroll
            for (int mt = 0; mt < 4; mt++) {
                #pragma unroll
                for (int h = 0; h < 2; h++) {
                    int ri = mt * 2 + h;
                    int rl = wm * 64 + mt * 16 + qr + h * 8;
                    int gi = i0 + rl;
                    float d20 = fmaf(acc[mt][nt][h * 2],     -2.f, magi_r[ri] + mj0);
                    float d21 = fmaf(acc[mt][nt][h * 2 + 1], -2.f, magi_r[ri] + mj1);
                    float dist0 = sqrt_approx(d20);
                    float dist1 = sqrt_approx(d21);
                    __half2 dh = __floats2half2_rn(dist0, dist1);
                    __half2 eh = h2exp2(__hfma2(dh, kA, kB));
                    uint32_t eu = *(uint32_t*)&eh;
                    if (ti_r[ri] == tj0) {
                        int gj = j0 + cl;
                        if (gi < gj) {
                            int slot = atomicAdd(psn, 1);
                            if (slot < PB) {
                                psd[slot]  = dist0;
                                psij[slot] = ((unsigned)gi << 12) | (unsigned)gj;
                            }
                        }
                        eu &= 0xFFFF0000u;
                    }
                    if (ti_r[ri] == tj1) {
                        int gj = j0 + cl + 1;
                        if (gi < gj) {
                            int slot = atomicAdd(psn, 1);
                            if (slot < PB) {
                                psd[slot]  = dist1;
                                psij[slot] = ((unsigned)gi << 12) | (unsigned)gj;
                            }
                        }
                        eu &= 0x0000FFFFu;
                    }
                    row_h2[ri] = hadd2_u(row_h2[ri], eu);
                    col_h2[nt] = hadd2_u(col_h2[nt], eu);
                }
            }
        }

        float rowsum[8], colsum[8];
        #pragma unroll
        for (int k = 0; k < 8; k++) {
            float2 f = __half22float2(*(__half2*)&row_h2[k]);
            rowsum[k] = f.x + f.y;
        }
        #pragma unroll
        for (int nt = 0; nt < 4; nt++) {
            float2 f = __half22float2(*(__half2*)&col_h2[nt]);
            colsum[nt * 2]     = f.x;
            colsum[nt * 2 + 1] = f.y;
        }

        #pragma unroll
        for (int k = 0; k < 8; k++) {
            rowsum[k] += __shfl_xor_sync(0xffffffff, rowsum[k], 1);
            rowsum[k] += __shfl_xor_sync(0xffffffff, rowsum[k], 2);
            colsum[k] += __shfl_xor_sync(0xffffffff, colsum[k], 4);
            colsum[k] += __shfl_xor_sync(0xffffffff, colsum[k], 8);
            colsum[k] += __shfl_xor_sync(0xffffffff, colsum[k], 16);
        }
        if ((lane & 3) == 0) {
            #pragma unroll
            for (int mt = 0; mt < 4; mt++)
                #pragma unroll
                for (int h = 0; h < 2; h++)
                    atomicAdd(&rbuf[wm * 64 + mt * 16 + qr + h * 8],
                              rowsum[mt * 2 + h]);
        }
        if (lane < 4) {
            #pragma unroll
            for (int nt = 0; nt < 4; nt++)
                #pragma unroll
                for (int v = 0; v < 2; v++)
                    atomicAdd(&cbuf[wn * 32 + nt * 8 + lane * 2 + v],
                              colsum[nt * 2 + v]);
        }
        __syncthreads();

        if (tid < 128) {
            atomicAdd(&g_rowneg[i0 + tid], rbuf[tid]);
            if (i0 != j0) atomicAdd(&g_rowneg[j0 + tid], cbuf[tid]);
        }

        if (tid == 0) {
            int n = *psn; if (n > PB) n = PB;
            *(int*)(smem + OFF_PSBASE) = atomicAdd(&g_npairs, n);
        }
        __syncthreads();
        int n = *psn; if (n > PB) n = PB;
        int base = *(int*)(smem + OFF_PSBASE);
        for (int s = tid; s < n; s += 256) {
            g_pair_d[base + s]  = psd[s];
            g_pair_ij[base + s] = psij[s];
        }
        __syncthreads();                  // protect smem before next iter
    }

    // ---- software grid barrier (all NBLK CTAs are co-resident) ----
    if (tid == 0) {
        __threadfence();
        atomicAdd(&g_done, 1u);
        while (*(volatile unsigned*)&g_done < NBLK) __nanosleep(64);
    }
    __syncthreads();
    __threadfence();

    // ---- pair loss phase ----
    int np = atomicAdd(&g_npairs, 0);
    float sum = 0.f;
    for (int p = blockIdx.x * 256 + tid; p < np; p += NBLK * 256) {
        float dist  = __ldcg(&g_pair_d[p]);
        unsigned ij = __ldcg(&g_pair_ij[p]);
        int i = (int)(ij >> 12), j = (int)(ij & 4095u);
        float l = logf(__ldcg(&g_rowneg[i]) + __ldcg(&g_rowneg[j]))
                  + (1.0f - CEXP) + dist;
        if (l > 0.f) sum += l * l;
    }
    #pragma unroll
    for (int off = 16; off; off >>= 1) sum += __shfl_xor_sync(0xffffffff, sum, off);
    __shared__ float ws[8];
    __shared__ int lastf;
    if ((tid & 31) == 0) ws[tid >> 5] = sum;
    __syncthreads();
    if (tid < 8) {
        float s = ws[tid];
        #pragma unroll
        for (int off = 4; off; off >>= 1) s += __shfl_xor_sync(0xff, s, off);
        if (tid == 0) {
            if (s != 0.f) atomicAdd(&g_loss, (double)s);
            __threadfence();
            unsigned d = atomicAdd(&g_done2, 1u);
            lastf = (d == NBLK - 1) ? 1 : 0;
        }
    }
    __syncthreads();
    if (lastf) {
        __shared__ int h[NCLS];
        if (tid < NCLS) h[tid] = 0;
        __syncthreads();
        for (int r = tid; r < B; r += 256)
            atomicAdd(&h[g_t32[r]], 1);
        __syncthreads();
        if (tid == 0) {
            long long total = 0;
            #pragma unroll
            for (int c = 0; c < NCLS; c++) {
                long long n = h[c];
                total += n * (n - 1) / 2;
            }
            out[0] = (float)(g_loss / (2.0 * (double)total));
        }
    }
}

// ---------------------------------------------------------------------------
extern "C" void kernel_launch(void* const* d_in, const int* in_sizes, int n_in,
                              void* d_out, int out_size) {
    const float* X   = (const float*)d_in[0];
    const int*   T   = (const int*)d_in[1];
    float*       out = (float*)d_out;

    cudaFuncSetAttribute(k_dist, cudaFuncAttributeMaxDynamicSharedMemorySize,
                         SMEM_TOTAL);

    k_prep<<<B / 8, 256>>>(X, T);
    k_dist<<<NBLK, 256, SMEM_TOTAL>>>(out);
}

// round 16
// speedup vs baseline: 2.3787x; 2.3787x over previous
#include <cuda_runtime.h>
#include <cuda_fp16.h>
#include <math.h>
#include <stdint.h>

#define B 4096
#define D 128
#define NT 32              // 4096 / 128 tiles per dimension
#define NCLS 64
#define PB 1024
#define PAIR_CAP (1 << 20)
#define LOSS_GRID 512
// exp offset: accumulate exp(CEXP - dist); k_loss adds (1 - CEXP) back in log
#define CEXP 16.0f

// ---- scratch (device globals; no allocation allowed) ----
__device__ float    g_rowneg[B];
__device__ float    g_mag[B];
__device__ int      g_t32[B];
__device__ int      g_npairs;
__device__ unsigned g_done;
__device__ float    g_pair_d[PAIR_CAP];
__device__ unsigned g_pair_ij[PAIR_CAP];
__device__ double   g_loss;
__device__ __align__(256) __half g_h16[(size_t)B * D];

static __device__ __forceinline__ uint32_t smem_u32(const void* p) {
    uint32_t a;
    asm("{ .reg .u64 t; cvta.to.shared.u64 t, %1; cvt.u32.u64 %0, t; }"
        : "=r"(a) : "l"(p));
    return a;
}

// ---- smem: full-K tiles A,B 128 x 128 fp16, row stride 272 B ----
#define LDT 272
#define TILE_B 34816       // 128 * 272
#define OFF_A    0
#define OFF_B    34816
#define OFF_MAGI 69632
#define OFF_MAGJ 70144
#define OFF_TI   70656
#define OFF_TJ   71168
#define OFF_RBUF 71680
#define OFF_CBUF 72192
#define OFF_PSD  72704
#define OFF_PSIJ 76800
#define OFF_PSN  80896
#define OFF_PSBASE 80900
#define SMEM_TOTAL 80960

#define LDSM4(r0, r1, r2, r3, a)                                         \
    asm volatile("ldmatrix.sync.aligned.m8n8.x4.shared.b16 "             \
                 "{%0,%1,%2,%3}, [%4];"                                  \
                 : "=r"(r0), "=r"(r1), "=r"(r2), "=r"(r3) : "r"(a))

#define MMA_F16(c, a0, a1, a2, a3, b0, b1)                               \
    asm volatile("mma.sync.aligned.m16n8k16.row.col.f32.f16.f16.f32 "    \
                 "{%0,%1,%2,%3}, {%4,%5,%6,%7}, {%8,%9}, {%0,%1,%2,%3};" \
                 : "+f"((c)[0]), "+f"((c)[1]), "+f"((c)[2]), "+f"((c)[3])\
                 : "r"(a0), "r"(a1), "r"(a2), "r"(a3), "r"(b0), "r"(b1))

#define CP_ASYNC16(s, g)                                                 \
    asm volatile("cp.async.cg.shared.global [%0], [%1], 16;"             \
                 :: "r"(s), "l"(g))
#define CP_COMMIT() asm volatile("cp.async.commit_group;" ::: "memory")
#define CP_WAIT0()  asm volatile("cp.async.wait_group 0;" ::: "memory")

static __device__ __forceinline__ uint32_t pack_h2(float lo, float hi) {
    uint32_t r;
    asm("cvt.rn.f16x2.f32 %0, %1, %2;" : "=r"(r) : "f"(hi), "f"(lo));
    return r;
}
static __device__ __forceinline__ float sqrt_approx(float x) {
    float r;
    asm("sqrt.approx.f32 %0, %1;" : "=f"(r) : "f"(x));
    return r;
}
static __device__ __forceinline__ uint32_t hadd2_u(uint32_t a, uint32_t b) {
    uint32_t r;
    asm("add.rn.f16x2 %0, %1, %2;" : "=r"(r) : "r"(a), "r"(b));
    return r;
}

// ---------------------------------------------------------------------------
// K1: fused prep — fp16 copy, exact fp32 magnitudes, labels, zero scalars.
//     Each warp handles 4 rows with batched loads (MLP=4).
// ---------------------------------------------------------------------------
__global__ void __launch_bounds__(256) k_prep(const float* __restrict__ X,
                                              const int* __restrict__ T) {
    int warp = threadIdx.x >> 5, lane = threadIdx.x & 31;
    int row0 = blockIdx.x * 8 + warp;        // grid 128 -> rows 0..1023
    float4 v[4];
    #pragma unroll
    for (int r = 0; r < 4; r++)
        v[r] = ((const float4*)(X + (size_t)(row0 + r * 1024) * D))[lane];

    #pragma unroll
    for (int r = 0; r < 4; r++) {
        int row = row0 + r * 1024;
        uint2 hp = { pack_h2(v[r].x, v[r].y), pack_h2(v[r].z, v[r].w) };
        ((uint2*)(g_h16 + (size_t)row * D))[lane] = hp;
        float s = v[r].x * v[r].x + v[r].y * v[r].y
                + v[r].z * v[r].z + v[r].w * v[r].w;
        #pragma unroll
        for (int off = 16; off; off >>= 1)
            s += __shfl_xor_sync(0xffffffff, s, off);
        if (lane == 0) {
            g_mag[row]    = s;
            g_t32[row]    = T[row] & (NCLS - 1);
            g_rowneg[row] = 0.f;
        }
    }
    if (blockIdx.x == 0 && threadIdx.x == 0) {
        g_loss = 0.0; g_npairs = 0; g_done = 0u;
    }
}

// ---------------------------------------------------------------------------
// K2: 128x128 Gram tile, fp16 mma.sync, full-K single load, f16x2 epilogue.
//     (verified R14 version, unchanged)
// ---------------------------------------------------------------------------
__global__ void __launch_bounds__(256, 2) k_dist() {
    extern __shared__ char smem[];
    uint32_t sb = smem_u32(smem);
    int tid = threadIdx.x;

    if (tid == 0) *(int*)(smem + OFF_PSN) = 0;

    // triangular block decode -> (bi, bj), bi <= bj
    int idx = blockIdx.x, bi = 0, rem = idx;
    while (rem >= NT - bi) { rem -= NT - bi; bi++; }
    int bj = bi + rem;
    int i0 = bi * 128, j0 = bj * 128;

    // issue the FULL K=128 tiles via cp.async
    #pragma unroll
    for (int it = 0; it < 16; it++) {
        int e    = it * 256 + tid;       // 0..4095 16B ops
        int tile = e >> 11;              // 0=A, 1=B
        int w    = e & 2047;
        int r    = w >> 4, kc = w & 15;
        int row0 = tile ? j0 : i0;
        CP_ASYNC16(sb + tile * TILE_B + r * LDT + kc * 16,
                   g_h16 + (size_t)(row0 + r) * D + kc * 8);
    }
    CP_COMMIT();

    float* magis = (float*)(smem + OFF_MAGI);
    float* magjs = (float*)(smem + OFF_MAGJ);
    int*   tis   = (int*)(smem + OFF_TI);
    int*   tjs   = (int*)(smem + OFF_TJ);
    float* rbuf  = (float*)(smem + OFF_RBUF);
    float* cbuf  = (float*)(smem + OFF_CBUF);

    if (tid < 128) {
        magis[tid] = g_mag[i0 + tid];
        magjs[tid] = g_mag[j0 + tid];
        tis[tid]   = g_t32[i0 + tid];
        tjs[tid]   = g_t32[j0 + tid];
        rbuf[tid] = 0.f; cbuf[tid] = 0.f;
    }

    int wid = tid >> 5, lane = tid & 31;
    int wm = wid & 1, wn = wid >> 1;      // 2 x 4 warp grid, 64x32 each

    float acc[4][4][4];
    #pragma unroll
    for (int mt = 0; mt < 4; mt++)
        #pragma unroll
        for (int nt = 0; nt < 4; nt++)
            #pragma unroll
            for (int q = 0; q < 4; q++) acc[mt][nt][q] = 0.f;

    uint32_t aRowOff = ((lane & 7) + ((lane >> 3) & 1) * 8) * LDT + (lane >> 4) * 16;
    uint32_t bRowOff = ((lane & 7) + (lane >> 4) * 8) * LDT + ((lane >> 3) & 1) * 16;
    uint32_t aBase = sb + OFF_A + wm * 64 * LDT + aRowOff;
    uint32_t bBase = sb + OFF_B + wn * 32 * LDT + bRowOff;

    CP_WAIT0();
    __syncthreads();                      // single barrier before mainloop

    #pragma unroll
    for (int ks = 0; ks < 8; ks++) {
        uint32_t ko = ks * 32;
        uint32_t bh[8];
        LDSM4(bh[0], bh[1], bh[2], bh[3], bBase + ko);
        LDSM4(bh[4], bh[5], bh[6], bh[7], bBase + 16 * LDT + ko);
        #pragma unroll
        for (int mt = 0; mt < 4; mt++) {
            uint32_t ah[4];
            LDSM4(ah[0], ah[1], ah[2], ah[3], aBase + mt * 16 * LDT + ko);
            #pragma unroll
            for (int nt = 0; nt < 4; nt++)
                MMA_F16(acc[mt][nt], ah[0], ah[1], ah[2], ah[3],
                        bh[nt * 2], bh[nt * 2 + 1]);
        }
    }

    // --- f16x2 register epilogue ---
    int qr = lane >> 2, qc2 = (lane & 3) * 2;
    float* psd = (float*)(smem + OFF_PSD);
    unsigned* psij = (unsigned*)(smem + OFF_PSIJ);
    int* psn = (int*)(smem + OFF_PSN);

    float magi_r[8]; int ti_r[8];
    #pragma unroll
    for (int mt = 0; mt < 4; mt++)
        #pragma unroll
        for (int h = 0; h < 2; h++) {
            int rl = wm * 64 + mt * 16 + qr + h * 8;
            magi_r[mt * 2 + h] = magis[rl];
            ti_r[mt * 2 + h]   = tis[rl];
        }

    uint32_t row_h2[8] = {0,0,0,0,0,0,0,0};
    uint32_t col_h2[4] = {0,0,0,0};
    const __half2 kA = __floats2half2_rn(-1.44269504f, -1.44269504f);
    const __half2 kB = __floats2half2_rn(CEXP * 1.44269504f, CEXP * 1.44269504f);

    #pragma unroll
    for (int nt = 0; nt < 4; nt++) {
        int cl = wn * 32 + nt * 8 + qc2;
        float mj0 = magjs[cl], mj1 = magjs[cl + 1];
        int   tj0 = tjs[cl],   tj1 = tjs[cl + 1];
        #pragma unroll
        for (int mt = 0; mt < 4; mt++) {
            #pragma unroll
            for (int h = 0; h < 2; h++) {
                int ri = mt * 2 + h;
                int rl = wm * 64 + mt * 16 + qr + h * 8;
                int gi = i0 + rl;
                float d20 = fmaf(acc[mt][nt][h * 2],     -2.f, magi_r[ri] + mj0);
                float d21 = fmaf(acc[mt][nt][h * 2 + 1], -2.f, magi_r[ri] + mj1);
                float dist0 = sqrt_approx(d20);
                float dist1 = sqrt_approx(d21);
                __half2 dh = __floats2half2_rn(dist0, dist1);
                __half2 eh = h2exp2(__hfma2(dh, kA, kB));
                uint32_t eu = *(uint32_t*)&eh;
                if (ti_r[ri] == tj0) {
                    int gj = j0 + cl;
                    if (gi < gj) {
                        int slot = atomicAdd(psn, 1);
                        if (slot < PB) {
                            psd[slot]  = dist0;
                            psij[slot] = ((unsigned)gi << 12) | (unsigned)gj;
                        }
                    }
                    eu &= 0xFFFF0000u;
                }
                if (ti_r[ri] == tj1) {
                    int gj = j0 + cl + 1;
                    if (gi < gj) {
                        int slot = atomicAdd(psn, 1);
                        if (slot < PB) {
                            psd[slot]  = dist1;
                            psij[slot] = ((unsigned)gi << 12) | (unsigned)gj;
                        }
                    }
                    eu &= 0x0000FFFFu;
                }
                row_h2[ri]  = hadd2_u(row_h2[ri], eu);
                col_h2[nt]  = hadd2_u(col_h2[nt], eu);
            }
        }
    }

    float rowsum[8], colsum[8];
    #pragma unroll
    for (int k = 0; k < 8; k++) {
        float2 f = __half22float2(*(__half2*)&row_h2[k]);
        rowsum[k] = f.x + f.y;
    }
    #pragma unroll
    for (int nt = 0; nt < 4; nt++) {
        float2 f = __half22float2(*(__half2*)&col_h2[nt]);
        colsum[nt * 2]     = f.x;
        colsum[nt * 2 + 1] = f.y;
    }

    #pragma unroll
    for (int k = 0; k < 8; k++) {
        rowsum[k] += __shfl_xor_sync(0xffffffff, rowsum[k], 1);
        rowsum[k] += __shfl_xor_sync(0xffffffff, rowsum[k], 2);
        colsum[k] += __shfl_xor_sync(0xffffffff, colsum[k], 4);
        colsum[k] += __shfl_xor_sync(0xffffffff, colsum[k], 8);
        colsum[k] += __shfl_xor_sync(0xffffffff, colsum[k], 16);
    }
    if ((lane & 3) == 0) {
        #pragma unroll
        for (int mt = 0; mt < 4; mt++)
            #pragma unroll
            for (int h = 0; h < 2; h++)
                atomicAdd(&rbuf[wm * 64 + mt * 16 + qr + h * 8],
                          rowsum[mt * 2 + h]);
    }
    if (lane < 4) {
        #pragma unroll
        for (int nt = 0; nt < 4; nt++)
            #pragma unroll
            for (int v = 0; v < 2; v++)
                atomicAdd(&cbuf[wn * 32 + nt * 8 + lane * 2 + v],
                          colsum[nt * 2 + v]);
    }
    __syncthreads();

    if (tid < 128) {
        atomicAdd(&g_rowneg[i0 + tid], rbuf[tid]);
        if (bi != bj) atomicAdd(&g_rowneg[j0 + tid], cbuf[tid]);
    }

    // flush positive pairs: one global atomic + coalesced copy
    if (tid == 0) {
        int n = *psn; if (n > PB) n = PB;
        *(int*)(smem + OFF_PSBASE) = atomicAdd(&g_npairs, n);
    }
    __syncthreads();
    int n = *psn; if (n > PB) n = PB;
    int base = *(int*)(smem + OFF_PSBASE);
    for (int s = tid; s < n; s += 256) {
        g_pair_d[base + s]  = psd[s];
        g_pair_ij[base + s] = psij[s];
    }
}

// ---------------------------------------------------------------------------
// K3: hinge^2 over compacted pairs (+ offset fixup) + fused finalize
// ---------------------------------------------------------------------------
__global__ void __launch_bounds__(256) k_loss(float* __restrict__ out) {
    int np = g_npairs;
    float sum = 0.f;
    for (int p = blockIdx.x * 256 + threadIdx.x; p < np; p += LOSS_GRID * 256) {
        float dist  = g_pair_d[p];
        unsigned ij = g_pair_ij[p];
        int i = (int)(ij >> 12), j = (int)(ij & 4095u);
        float l = logf(g_rowneg[i] + g_rowneg[j]) + (1.0f - CEXP) + dist;
        if (l > 0.f) sum += l * l;
    }
    #pragma unroll
    for (int off = 16; off; off >>= 1) sum += __shfl_xor_sync(0xffffffff, sum, off);
    __shared__ float ws[8];
    __shared__ int last;
    if ((threadIdx.x & 31) == 0) ws[threadIdx.x >> 5] = sum;
    __syncthreads();
    if (threadIdx.x < 8) {
        float s = ws[threadIdx.x];
        #pragma unroll
        for (int off = 4; off; off >>= 1) s += __shfl_xor_sync(0xff, s, off);
        if (threadIdx.x == 0) {
            if (s != 0.f) atomicAdd(&g_loss, (double)s);
            __threadfence();
            unsigned t = atomicAdd(&g_done, 1u);
            last = (t == LOSS_GRID - 1) ? 1 : 0;
        }
    }
    __syncthreads();
    if (last) {
        __shared__ int h[NCLS];
        if (threadIdx.x < NCLS) h[threadIdx.x] = 0;
        __syncthreads();
        for (int r = threadIdx.x; r < B; r += 256)
            atomicAdd(&h[g_t32[r]], 1);
        __syncthreads();
        if (threadIdx.x == 0) {
            long long total = 0;
            #pragma unroll
            for (int c = 0; c < NCLS; c++) {
                long long n = h[c];
                total += n * (n - 1) / 2;
            }
            out[0] = (float)(g_loss / (2.0 * (double)total));
        }
    }
}

// ---------------------------------------------------------------------------
extern "C" void kernel_launch(void* const* d_in, const int* in_sizes, int n_in,
                              void* d_out, int out_size) {
    const float* X   = (const float*)d_in[0];
    const int*   T   = (const int*)d_in[1];
    float*       out = (float*)d_out;

    cudaFuncSetAttribute(k_dist, cudaFuncAttributeMaxDynamicSharedMemorySize,
                         SMEM_TOTAL);

    k_prep<<<128, 256>>>(X, T);
    k_dist<<<NT * (NT + 1) / 2, 256, SMEM_TOTAL>>>();
    k_loss<<<LOSS_GRID, 256>>>(out);
}